// round 6
// baseline (speedup 1.0000x reference)
#include <cuda_runtime.h>

#define NN 40000
#define EE 600000
#define HH 128
#define GG 32
#define CC 6

// ---- scratch (device globals: no allocation allowed) ----
__device__ float g_b1[NN * HH];
__device__ float g_b2[NN * HH];
__device__ float g_b3[NN * HH];
__device__ float g_dinv[NN];
__device__ float g_emb[GG * HH];
__device__ float g_cnt[GG];
__device__ int   g_deg[NN];
__device__ int   g_rowstart[NN + 1];
__device__ int   g_cursor[NN];
__device__ int   g_csrsrc[EE];
__device__ float g_wnorm[EE];
__device__ unsigned g_wfrag[7 * 2 * 16384];   // 7 matrices, hi[16384] + lo[16384] each

// ---------------- small utility kernels ----------------
__global__ void k_zero4(float* __restrict__ p, int n4) {
    int i = blockIdx.x * blockDim.x + threadIdx.x;
    if (i < n4) ((float4*)p)[i] = make_float4(0.f, 0.f, 0.f, 0.f);
}

__global__ void k_zero_int(int* __restrict__ p, int n) {
    int i = blockIdx.x * blockDim.x + threadIdx.x;
    if (i < n) p[i] = 0;
}

__global__ void k_hist(const int* __restrict__ dst, int* __restrict__ cnt) {
    int e = blockIdx.x * blockDim.x + threadIdx.x;
    if (e < EE) atomicAdd(&cnt[dst[e]], 1);
}

// single block, 1024 threads: exclusive scan of deg -> row_start, cursor; dinv = rsqrt(deg+1)
__global__ __launch_bounds__(1024) void k_scan(const int* __restrict__ cnt,
                                               int* __restrict__ row_start,
                                               int* __restrict__ cursor,
                                               float* __restrict__ dinv) {
    __shared__ int s[1024];
    const int CH = 40;
    int t = threadIdx.x;
    int base = t * CH;
    int sum = 0;
#pragma unroll
    for (int i = 0; i < CH; ++i) {
        int idx = base + i;
        if (idx < NN) sum += cnt[idx];
    }
    s[t] = sum;
    __syncthreads();
#pragma unroll
    for (int off = 1; off < 1024; off <<= 1) {
        int v = 0;
        if (t >= off) v = s[t - off];
        __syncthreads();
        if (t >= off) s[t] += v;
        __syncthreads();
    }
    int pre = (t == 0) ? 0 : s[t - 1];
#pragma unroll
    for (int i = 0; i < CH; ++i) {
        int idx = base + i;
        if (idx < NN) {
            row_start[idx] = pre;
            cursor[idx] = pre;
            dinv[idx] = rsqrtf((float)(cnt[idx] + 1));
            pre += cnt[idx];
        }
    }
    if (t == 1023) row_start[NN] = EE;
}

__global__ void k_fill(const int* __restrict__ src, const int* __restrict__ dst,
                       const float* __restrict__ dinv,
                       int* __restrict__ cursor, int* __restrict__ csr_src,
                       float* __restrict__ wnorm) {
    int e = blockIdx.x * blockDim.x + threadIdx.x;
    if (e >= EE) return;
    int s = src[e];
    int d = dst[e];
    int pos = atomicAdd(&cursor[d], 1);
    csr_src[pos] = s;
    wnorm[pos] = dinv[s] * dinv[d];
}

// ---------------- tf32 helpers ----------------
__device__ __forceinline__ unsigned f2tf(float f) {
    unsigned u;
    asm("cvt.rna.tf32.f32 %0, %1;" : "=r"(u) : "f"(f));
    return u;
}

// W fragment layout: idx(k,n) = ((k>>3)*16 + (n>>3))*64 + (n&7)*8 + (k&3)*2 + ((k>>2)&1)
// hi at [mat*32768 + idx], lo at [mat*32768 + 16384 + idx]
__global__ void k_prep_w(const float* __restrict__ w0, const float* __restrict__ w1,
                         const float* __restrict__ w2, const float* __restrict__ w3,
                         const float* __restrict__ w4, const float* __restrict__ w5,
                         const float* __restrict__ w6, unsigned* __restrict__ wf) {
    int id = blockIdx.x * blockDim.x + threadIdx.x;     // 0..16383
    int mat = blockIdx.y;
    const float* w;
    switch (mat) {
        case 0: w = w0; break; case 1: w = w1; break; case 2: w = w2; break;
        case 3: w = w3; break; case 4: w = w4; break; case 5: w = w5; break;
        default: w = w6; break;
    }
    int k = id >> 7;
    int n = id & 127;
    float v = w[k * HH + n];
    int idx = ((k >> 3) * 16 + (n >> 3)) * 64 + (n & 7) * 8 + (k & 3) * 2 + ((k >> 2) & 1);
    unsigned h = f2tf(v);
    wf[mat * 32768 + idx] = h;
    wf[mat * 32768 + 16384 + idx] = f2tf(v - __uint_as_float(h));
}

// ---------------- gather aggregation: one warp per node ----------------
__global__ __launch_bounds__(256) void k_gather(
    const float* __restrict__ x, float* __restrict__ out,
    const int* __restrict__ row_start, const int* __restrict__ csr_src,
    const float* __restrict__ wnorm)
{
    int node = (blockIdx.x * blockDim.x + threadIdx.x) >> 5;
    int lane = threadIdx.x & 31;
    if (node >= NN) return;
    int beg = row_start[node];
    int end = row_start[node + 1];

    float4 acc = make_float4(0.f, 0.f, 0.f, 0.f);
    int e = beg;
    for (; e + 1 < end; e += 2) {
        int s0 = csr_src[e], s1 = csr_src[e + 1];
        float4 v0 = ((const float4*)(x + (size_t)s0 * HH))[lane];
        float4 v1 = ((const float4*)(x + (size_t)s1 * HH))[lane];
        float w0 = 1.f, w1 = 1.f;
        if (wnorm) { w0 = wnorm[e]; w1 = wnorm[e + 1]; }
        acc.x = fmaf(v0.x, w0, acc.x); acc.y = fmaf(v0.y, w0, acc.y);
        acc.z = fmaf(v0.z, w0, acc.z); acc.w = fmaf(v0.w, w0, acc.w);
        acc.x = fmaf(v1.x, w1, acc.x); acc.y = fmaf(v1.y, w1, acc.y);
        acc.z = fmaf(v1.z, w1, acc.z); acc.w = fmaf(v1.w, w1, acc.w);
    }
    if (e < end) {
        int s0 = csr_src[e];
        float4 v0 = ((const float4*)(x + (size_t)s0 * HH))[lane];
        float w0 = wnorm ? wnorm[e] : 1.f;
        acc.x = fmaf(v0.x, w0, acc.x); acc.y = fmaf(v0.y, w0, acc.y);
        acc.z = fmaf(v0.z, w0, acc.z); acc.w = fmaf(v0.w, w0, acc.w);
    }

    float4* o = ((float4*)(out + (size_t)node * HH)) + lane;
    if (wnorm) {
        float4 cur = *o;
        acc.x += cur.x; acc.y += cur.y; acc.z += cur.z; acc.w += cur.w;
    }
    *o = acc;
}

// ---------------- 3xTF32 tensor-core GEMM (W fragments from gmem) ----------------
__device__ __forceinline__ void mma_tf32(float (&c)[4], const unsigned (&a)[4],
                                         unsigned b0, unsigned b1) {
    asm volatile(
        "mma.sync.aligned.m16n8k8.row.col.f32.tf32.tf32.f32 "
        "{%0,%1,%2,%3},{%4,%5,%6,%7},{%8,%9},{%0,%1,%2,%3};"
        : "+f"(c[0]), "+f"(c[1]), "+f"(c[2]), "+f"(c[3])
        : "r"(a[0]), "r"(a[1]), "r"(a[2]), "r"(a[3]), "r"(b0), "r"(b1));
}

#define AP 36   // A smem pitch
#define ASZ (128 * AP)

__global__ __launch_bounds__(256, 2) void k_gemm_tc(
    const float* __restrict__ A1, const unsigned* __restrict__ WF1,
    const float* __restrict__ A2, const unsigned* __restrict__ WF2,
    const float* __restrict__ bias_in,   // applied (with relu) to A1 convert
    const float* __restrict__ bias_out,
    const float* __restrict__ dinv,
    float* __restrict__ out1, float* __restrict__ out2, int relu_out)
{
    extern __shared__ unsigned sm[];
    unsigned* AH = sm;
    unsigned* AL = AH + ASZ;

    const int tid = threadIdx.x;
    const int wid = tid >> 5;
    const int lane = tid & 31;
    const int g = lane >> 2;
    const int t = lane & 3;
    const int warpM = wid >> 1;
    const int warpN = wid & 1;
    const int row0 = blockIdx.x * 128;

    const int ar = tid >> 3;            // A row within tile (+ i*32)
    const int ac4 = (tid & 7) * 4;      // A col quad

    float acc[2][8][4];
#pragma unroll
    for (int mi = 0; mi < 2; ++mi)
#pragma unroll
        for (int ni = 0; ni < 8; ++ni)
#pragma unroll
            for (int j = 0; j < 4; ++j) acc[mi][ni][j] = 0.f;

    const int npass = A2 ? 2 : 1;
    const int ntiles = npass * 4;

    float4 rA[4];
#pragma unroll
    for (int i = 0; i < 4; ++i) {
        int grow = row0 + ar + i * 32;
        rA[i] = make_float4(0.f, 0.f, 0.f, 0.f);
        if (grow < NN) rA[i] = *(const float4*)(A1 + (size_t)grow * HH + ac4);
    }

#pragma unroll 1
    for (int tile = 0; tile < ntiles; ++tile) {
        const int k0 = (tile & 3) * 32;
        const bool pre = (tile < 4) && (bias_in != nullptr);
        const unsigned* WF = (tile >> 2) ? WF2 : WF1;

        __syncthreads();
#pragma unroll
        for (int i = 0; i < 4; ++i) {
            float4 v = rA[i];
            if (pre) {
                v.x = fmaxf(v.x + bias_in[k0 + ac4 + 0], 0.f);
                v.y = fmaxf(v.y + bias_in[k0 + ac4 + 1], 0.f);
                v.z = fmaxf(v.z + bias_in[k0 + ac4 + 2], 0.f);
                v.w = fmaxf(v.w + bias_in[k0 + ac4 + 3], 0.f);
            }
            int bo = (ar + i * 32) * AP + ac4;
            float vv[4] = {v.x, v.y, v.z, v.w};
#pragma unroll
            for (int j = 0; j < 4; ++j) {
                unsigned h = f2tf(vv[j]);
                AH[bo + j] = h;
                AL[bo + j] = f2tf(vv[j] - __uint_as_float(h));
            }
        }
        __syncthreads();

        // prefetch next A tile
        if (tile + 1 < ntiles) {
            const int nt = tile + 1;
            const float* A = (nt >> 2) ? A2 : A1;
            const int nk0 = (nt & 3) * 32;
#pragma unroll
            for (int i = 0; i < 4; ++i) {
                int grow = row0 + ar + i * 32;
                rA[i] = make_float4(0.f, 0.f, 0.f, 0.f);
                if (grow < NN) rA[i] = *(const float4*)(A + (size_t)grow * HH + nk0 + ac4);
            }
        }

        const int ksg = (tile & 3) * 4;   // global k-octet base for fragments
#pragma unroll
        for (int ks = 0; ks < 4; ++ks) {
            int kb = ks * 8;
            unsigned ah[2][4], al[2][4];
#pragma unroll
            for (int mi = 0; mi < 2; ++mi) {
                int rb = (warpM * 32 + mi * 16 + g) * AP + kb + t;
                ah[mi][0] = AH[rb];
                ah[mi][1] = AH[rb + 8 * AP];
                ah[mi][2] = AH[rb + 4];
                ah[mi][3] = AH[rb + 8 * AP + 4];
                al[mi][0] = AL[rb];
                al[mi][1] = AL[rb + 8 * AP];
                al[mi][2] = AL[rb + 4];
                al[mi][3] = AL[rb + 8 * AP + 4];
            }
#pragma unroll
            for (int ni = 0; ni < 8; ++ni) {
                int fw = ((ksg + ks) * 16 + warpN * 8 + ni) * 64 + lane * 2;
                uint2 bh = *(const uint2*)(WF + fw);
                uint2 bl = *(const uint2*)(WF + 16384 + fw);
#pragma unroll
                for (int mi = 0; mi < 2; ++mi) {
                    mma_tf32(acc[mi][ni], ah[mi], bh.x, bh.y);
                    mma_tf32(acc[mi][ni], ah[mi], bl.x, bl.y);
                    mma_tf32(acc[mi][ni], al[mi], bh.x, bh.y);
                }
            }
        }
    }

    // ---- epilogue ----
#pragma unroll
    for (int mi = 0; mi < 2; ++mi) {
        int rbase = row0 + warpM * 32 + mi * 16 + g;
#pragma unroll
        for (int ni = 0; ni < 8; ++ni) {
            int col = warpN * 64 + ni * 8 + 2 * t;
            float c0 = acc[mi][ni][0], c1 = acc[mi][ni][1];
            float c2 = acc[mi][ni][2], c3 = acc[mi][ni][3];
            if (dinv) {
                if (rbase < NN) {
                    float w = dinv[rbase]; w *= w;
                    *(float2*)(out1 + (size_t)rbase * HH + col) = make_float2(c0, c1);
                    *(float2*)(out2 + (size_t)rbase * HH + col) = make_float2(c0 * w, c1 * w);
                }
                if (rbase + 8 < NN) {
                    float w = dinv[rbase + 8]; w *= w;
                    *(float2*)(out1 + (size_t)(rbase + 8) * HH + col) = make_float2(c2, c3);
                    *(float2*)(out2 + (size_t)(rbase + 8) * HH + col) = make_float2(c2 * w, c3 * w);
                }
            } else {
                float b0 = bias_out[col], b1 = bias_out[col + 1];
                c0 += b0; c1 += b1; c2 += b0; c3 += b1;
                if (relu_out) {
                    c0 = fmaxf(c0, 0.f); c1 = fmaxf(c1, 0.f);
                    c2 = fmaxf(c2, 0.f); c3 = fmaxf(c3, 0.f);
                }
                if (rbase < NN)
                    *(float2*)(out1 + (size_t)rbase * HH + col) = make_float2(c0, c1);
                if (rbase + 8 < NN)
                    *(float2*)(out1 + (size_t)(rbase + 8) * HH + col) = make_float2(c2, c3);
            }
        }
    }
}

// ---------------- pooling: one warp per node ----------------
__global__ void k_pool(const float* __restrict__ h, const int* __restrict__ batch,
                       float* __restrict__ emb, float* __restrict__ cnt) {
    int i = (blockIdx.x * blockDim.x + threadIdx.x) >> 5;
    int lane = threadIdx.x & 31;
    if (i >= NN) return;
    int g = batch[i];
    float4 v = ((const float4*)(h + (size_t)i * HH))[lane];
    atomicAdd(((float4*)(emb + (size_t)g * HH)) + lane, v);
    if (lane == 0) atomicAdd(&cnt[g], 1.0f);
}

// ---------------- final head: mean (+b5) + linear ----------------
__global__ void k_final(const float* __restrict__ lin_w, const float* __restrict__ lin_b,
                        const float* __restrict__ b5,
                        const float* __restrict__ emb, const float* __restrict__ cnt,
                        float* __restrict__ out) {
    __shared__ float se[GG * HH];
    int tid = threadIdx.x;
    for (int i = tid; i < GG * HH; i += blockDim.x) {
        int g = i >> 7;
        int c = i & 127;
        float v = emb[i] / fmaxf(cnt[g], 1.0f) + b5[c];
        se[i] = v;
        out[GG * CC + i] = v;
    }
    __syncthreads();
    for (int i = tid; i < GG * CC; i += blockDim.x) {
        int g = i / CC, c = i % CC;
        float s = lin_b[c];
        const float* e = &se[g * HH];
#pragma unroll 4
        for (int k = 0; k < HH; ++k) s = fmaf(e[k], lin_w[k * CC + c], s);
        out[i] = s;
    }
}

// ---------------- launch ----------------
extern "C" void kernel_launch(void* const* d_in, const int* in_sizes, int n_in,
                              void* d_out, int out_size) {
    const float* x      = (const float*)d_in[0];
    const int*   ei     = (const int*)d_in[1];
    const int*   batch  = (const int*)d_in[2];
    const float* w1r    = (const float*)d_in[3];
    const float* w1rel  = (const float*)d_in[4];
    const float* b1     = (const float*)d_in[5];
    const float* w2r    = (const float*)d_in[6];
    const float* w2rel  = (const float*)d_in[7];
    const float* b2     = (const float*)d_in[8];
    const float* w3     = (const float*)d_in[9];
    const float* b3     = (const float*)d_in[10];
    const float* w4     = (const float*)d_in[11];
    const float* b4     = (const float*)d_in[12];
    const float* w5     = (const float*)d_in[13];
    const float* b5     = (const float*)d_in[14];
    const float* lin_w  = (const float*)d_in[15];
    const float* lin_b  = (const float*)d_in[16];
    float* out = (float*)d_out;

    const int* src = ei;
    const int* dst = ei + EE;

    float *B1, *B2, *B3, *DINV, *EMB, *CNT, *WNORM;
    int *DEG, *ROWS, *CUR, *CSRC;
    unsigned* WFRAG;
    cudaGetSymbolAddress((void**)&B1, g_b1);
    cudaGetSymbolAddress((void**)&B2, g_b2);
    cudaGetSymbolAddress((void**)&B3, g_b3);
    cudaGetSymbolAddress((void**)&DINV, g_dinv);
    cudaGetSymbolAddress((void**)&EMB, g_emb);
    cudaGetSymbolAddress((void**)&CNT, g_cnt);
    cudaGetSymbolAddress((void**)&DEG, g_deg);
    cudaGetSymbolAddress((void**)&ROWS, g_rowstart);
    cudaGetSymbolAddress((void**)&CUR, g_cursor);
    cudaGetSymbolAddress((void**)&CSRC, g_csrsrc);
    cudaGetSymbolAddress((void**)&WNORM, g_wnorm);
    cudaGetSymbolAddress((void**)&WFRAG, g_wfrag);

    const int SMEM = 2 * ASZ * 4;   // 36864 B
    cudaFuncSetAttribute(k_gemm_tc, cudaFuncAttributeMaxDynamicSharedMemorySize, SMEM);

    const int NB  = (NN + 255) / 256;
    const int EB  = (EE + 255) / 256;
    const int GWB = (NN * 32 + 255) / 256;
    const int GMB = (NN + 127) / 128;          // 313

    // matrix slots: 0=w1r 1=w1rel 2=w2r 3=w2rel 4=w3 5=w4 6=w5
    const unsigned* WF_w1r   = WFRAG + 0 * 32768;
    const unsigned* WF_w1rel = WFRAG + 1 * 32768;
    const unsigned* WF_w2r   = WFRAG + 2 * 32768;
    const unsigned* WF_w2rel = WFRAG + 3 * 32768;
    const unsigned* WF_w3    = WFRAG + 4 * 32768;
    const unsigned* WF_w4    = WFRAG + 5 * 32768;
    const unsigned* WF_w5    = WFRAG + 6 * 32768;

    // ---- weight prep + CSR build ----
    k_prep_w<<<dim3(64, 7), 256>>>(w1r, w1rel, w2r, w2rel, w3, w4, w5, WFRAG);
    k_zero_int<<<NB, 256>>>(DEG, NN);
    k_hist<<<EB, 256>>>(dst, DEG);
    k_scan<<<1, 1024>>>(DEG, ROWS, CUR, DINV);
    k_fill<<<EB, 256>>>(src, dst, DINV, CUR, CSRC, WNORM);

    // ---- L1: GraphConv ----
    k_gather<<<GWB, 256>>>(x, B1, ROWS, CSRC, nullptr);
    k_gemm_tc<<<GMB, 256, SMEM>>>(x, WF_w1r, B1, WF_w1rel, nullptr, b1, nullptr, B2, nullptr, 1);

    // ---- L2: GraphConv ----
    k_gather<<<GWB, 256>>>(B2, B1, ROWS, CSRC, nullptr);
    k_gemm_tc<<<GMB, 256, SMEM>>>(B2, WF_w2r, B1, WF_w2rel, nullptr, b2, nullptr, B3, nullptr, 1);

    // ---- L3: GCNConv ----  raw h -> B2, self-term h*dinv^2 -> B1; gather adds into B1
    k_gemm_tc<<<GMB, 256, SMEM>>>(B3, WF_w3, nullptr, nullptr, nullptr, nullptr, DINV, B2, B1, 0);
    k_gather<<<GWB, 256>>>(B2, B1, ROWS, CSRC, WNORM);

    // ---- L4: GCNConv (input +b3, relu on load) ----
    k_gemm_tc<<<GMB, 256, SMEM>>>(B1, WF_w4, nullptr, nullptr, b3, nullptr, DINV, B2, B3, 0);
    k_gather<<<GWB, 256>>>(B2, B3, ROWS, CSRC, WNORM);

    // ---- L5: GCNConv (input +b4, relu on load) ----
    k_gemm_tc<<<GMB, 256, SMEM>>>(B3, WF_w5, nullptr, nullptr, b4, nullptr, DINV, B2, B1, 0);
    k_gather<<<GWB, 256>>>(B2, B1, ROWS, CSRC, WNORM);

    // ---- pooling + head (b5 folded into final mean) ----
    k_zero4<<<(GG * HH / 4 + 255) / 256, 256>>>(EMB, GG * HH / 4);
    k_zero4<<<1, 32>>>(CNT, GG / 4);
    k_pool<<<GWB, 256>>>(B1, batch, EMB, CNT);
    k_final<<<1, 512>>>(lin_w, lin_b, b5, EMB, CNT, out);
}

// round 7
// speedup vs baseline: 1.3894x; 1.3894x over previous
#include <cuda_runtime.h>

#define NN 40000
#define EE 600000
#define HH 128
#define GG 32
#define CC 6
#define NB2 157   // ceil(NN/256)

// ---- scratch (device globals: no allocation allowed) ----
__device__ float g_b1[NN * HH];
__device__ float g_b2[NN * HH];
__device__ float g_b3[NN * HH];
__device__ float g_dinv[NN];
__device__ float g_emb[GG * HH];
__device__ float g_cnt[GG];
__device__ int   g_deg[NN];
__device__ int   g_rowstart[NN + 1];
__device__ int   g_cursor[NN];
__device__ int   g_csrsrc[EE];
__device__ float g_wnorm[EE];
__device__ int   g_bsum[NB2];
__device__ int   g_bscan[NB2];

// ---------------- small utility kernels ----------------
__global__ void k_zero4(float* __restrict__ p, int n4) {
    int i = blockIdx.x * blockDim.x + threadIdx.x;
    if (i < n4) ((float4*)p)[i] = make_float4(0.f, 0.f, 0.f, 0.f);
}

__global__ void k_zero_int(int* __restrict__ p, int n) {
    int i = blockIdx.x * blockDim.x + threadIdx.x;
    if (i < n) p[i] = 0;
}

__global__ void k_hist(const int* __restrict__ dst, int* __restrict__ cnt) {
    int e = blockIdx.x * blockDim.x + threadIdx.x;
    if (e < EE) atomicAdd(&cnt[dst[e]], 1);
}

// ---- 3-stage parallel exclusive scan over degrees ----
__global__ void k_bsum(const int* __restrict__ deg, int* __restrict__ bsum) {
    __shared__ int s[8];
    int i = blockIdx.x * 256 + threadIdx.x;
    int v = (i < NN) ? deg[i] : 0;
#pragma unroll
    for (int o = 16; o > 0; o >>= 1) v += __shfl_down_sync(0xffffffffu, v, o);
    if ((threadIdx.x & 31) == 0) s[threadIdx.x >> 5] = v;
    __syncthreads();
    if (threadIdx.x < 8) {
        int w = s[threadIdx.x];
#pragma unroll
        for (int o = 4; o > 0; o >>= 1) w += __shfl_down_sync(0xffu, w, o);
        if (threadIdx.x == 0) bsum[blockIdx.x] = w;
    }
}

__global__ void k_bscan(const int* __restrict__ bsum, int* __restrict__ bscan) {
    __shared__ int s[256];
    int t = threadIdx.x;
    int v = (t < NB2) ? bsum[t] : 0;
    s[t] = v;
    __syncthreads();
#pragma unroll
    for (int off = 1; off < 256; off <<= 1) {
        int u = 0;
        if (t >= off) u = s[t - off];
        __syncthreads();
        if (t >= off) s[t] += u;
        __syncthreads();
    }
    if (t < NB2) bscan[t] = s[t] - v;    // exclusive
}

__global__ void k_writeoff(const int* __restrict__ deg, const int* __restrict__ bscan,
                           int* __restrict__ row_start, int* __restrict__ cursor,
                           float* __restrict__ dinv) {
    __shared__ int s[256];
    int t = threadIdx.x;
    int i = blockIdx.x * 256 + t;
    int d = (i < NN) ? deg[i] : 0;
    s[t] = d;
    __syncthreads();
#pragma unroll
    for (int off = 1; off < 256; off <<= 1) {
        int u = 0;
        if (t >= off) u = s[t - off];
        __syncthreads();
        if (t >= off) s[t] += u;
        __syncthreads();
    }
    if (i < NN) {
        int excl = s[t] - d + bscan[blockIdx.x];
        row_start[i] = excl;
        cursor[i] = excl;
        dinv[i] = rsqrtf((float)(d + 1));
        if (i == NN - 1) row_start[NN] = EE;
    }
}

__global__ void k_fill(const int* __restrict__ src, const int* __restrict__ dst,
                       const float* __restrict__ dinv,
                       int* __restrict__ cursor, int* __restrict__ csr_src,
                       float* __restrict__ wnorm) {
    int e = blockIdx.x * blockDim.x + threadIdx.x;
    if (e >= EE) return;
    int s = src[e];
    int d = dst[e];
    int pos = atomicAdd(&cursor[d], 1);
    csr_src[pos] = s;
    wnorm[pos] = dinv[s] * dinv[d];
}

// ---------------- gather aggregation: one warp per node ----------------
__global__ __launch_bounds__(256) void k_gather(
    const float* __restrict__ x, float* __restrict__ out,
    const int* __restrict__ row_start, const int* __restrict__ csr_src,
    const float* __restrict__ wnorm)
{
    int node = (blockIdx.x * blockDim.x + threadIdx.x) >> 5;
    int lane = threadIdx.x & 31;
    if (node >= NN) return;
    int beg = row_start[node];
    int end = row_start[node + 1];

    float4 acc = make_float4(0.f, 0.f, 0.f, 0.f);
    int e = beg;
    for (; e + 1 < end; e += 2) {
        int s0 = csr_src[e], s1 = csr_src[e + 1];
        float4 v0 = ((const float4*)(x + (size_t)s0 * HH))[lane];
        float4 v1 = ((const float4*)(x + (size_t)s1 * HH))[lane];
        float w0 = 1.f, w1 = 1.f;
        if (wnorm) { w0 = wnorm[e]; w1 = wnorm[e + 1]; }
        acc.x = fmaf(v0.x, w0, acc.x); acc.y = fmaf(v0.y, w0, acc.y);
        acc.z = fmaf(v0.z, w0, acc.z); acc.w = fmaf(v0.w, w0, acc.w);
        acc.x = fmaf(v1.x, w1, acc.x); acc.y = fmaf(v1.y, w1, acc.y);
        acc.z = fmaf(v1.z, w1, acc.z); acc.w = fmaf(v1.w, w1, acc.w);
    }
    if (e < end) {
        int s0 = csr_src[e];
        float4 v0 = ((const float4*)(x + (size_t)s0 * HH))[lane];
        float w0 = wnorm ? wnorm[e] : 1.f;
        acc.x = fmaf(v0.x, w0, acc.x); acc.y = fmaf(v0.y, w0, acc.y);
        acc.z = fmaf(v0.z, w0, acc.z); acc.w = fmaf(v0.w, w0, acc.w);
    }

    float4* o = ((float4*)(out + (size_t)node * HH)) + lane;
    if (wnorm) {
        float4 cur = *o;
        acc.x += cur.x; acc.y += cur.y; acc.z += cur.z; acc.w += cur.w;
    }
    *o = acc;
}

// ---------------- 3xTF32 tensor-core GEMM (R5: smem staging + A/W reg prefetch) ----------------
__device__ __forceinline__ unsigned f2tf(float f) {
    unsigned u;
    asm("cvt.rna.tf32.f32 %0, %1;" : "=r"(u) : "f"(f));
    return u;
}

__device__ __forceinline__ void mma_tf32(float (&c)[4], const unsigned (&a)[4],
                                         unsigned b0, unsigned b1) {
    asm volatile(
        "mma.sync.aligned.m16n8k8.row.col.f32.tf32.tf32.f32 "
        "{%0,%1,%2,%3},{%4,%5,%6,%7},{%8,%9},{%0,%1,%2,%3};"
        : "+f"(c[0]), "+f"(c[1]), "+f"(c[2]), "+f"(c[3])
        : "r"(a[0]), "r"(a[1]), "r"(a[2]), "r"(a[3]), "r"(b0), "r"(b1));
}

#define AP 36   // A smem pitch
#define WP 136  // W smem pitch
#define ASZ (128 * AP)
#define WSZ (32 * WP)

__global__ __launch_bounds__(256, 2) void k_gemm_tc(
    const float* __restrict__ A1, const float* __restrict__ W1,
    const float* __restrict__ A2, const float* __restrict__ W2,
    const float* __restrict__ bias_in,
    const float* __restrict__ bias_out,
    const float* __restrict__ dinv,
    float* __restrict__ out1, float* __restrict__ out2, int relu_out)
{
    extern __shared__ unsigned sm[];
    unsigned* AH = sm;
    unsigned* AL = AH + ASZ;
    unsigned* WH = AL + ASZ;
    unsigned* WL = WH + WSZ;

    const int tid = threadIdx.x;
    const int wid = tid >> 5;
    const int lane = tid & 31;
    const int g = lane >> 2;
    const int t = lane & 3;
    const int warpM = wid >> 1;
    const int warpN = wid & 1;
    const int row0 = blockIdx.x * 128;

    const int ar = tid >> 3;
    const int ac4 = (tid & 7) * 4;
    const int wk = tid >> 5;
    const int wn4 = (tid & 31) * 4;

    float acc[2][8][4];
#pragma unroll
    for (int mi = 0; mi < 2; ++mi)
#pragma unroll
        for (int ni = 0; ni < 8; ++ni)
#pragma unroll
            for (int j = 0; j < 4; ++j) acc[mi][ni][j] = 0.f;

    const int npass = A2 ? 2 : 1;
    const int ntiles = npass * 4;

    float4 rA[4], rW[4];
    {
#pragma unroll
        for (int i = 0; i < 4; ++i) {
            int grow = row0 + ar + i * 32;
            rA[i] = make_float4(0.f, 0.f, 0.f, 0.f);
            if (grow < NN) rA[i] = *(const float4*)(A1 + (size_t)grow * HH + ac4);
        }
#pragma unroll
        for (int i = 0; i < 4; ++i)
            rW[i] = *(const float4*)(W1 + (size_t)(wk + i * 8) * HH + wn4);
    }

#pragma unroll 1
    for (int tile = 0; tile < ntiles; ++tile) {
        const int k0 = (tile & 3) * 32;
        const bool pre = (tile < 4) && (bias_in != nullptr);

        __syncthreads();
#pragma unroll
        for (int i = 0; i < 4; ++i) {
            float4 v = rA[i];
            if (pre) {
                v.x = fmaxf(v.x + bias_in[k0 + ac4 + 0], 0.f);
                v.y = fmaxf(v.y + bias_in[k0 + ac4 + 1], 0.f);
                v.z = fmaxf(v.z + bias_in[k0 + ac4 + 2], 0.f);
                v.w = fmaxf(v.w + bias_in[k0 + ac4 + 3], 0.f);
            }
            int bo = (ar + i * 32) * AP + ac4;
            float vv[4] = {v.x, v.y, v.z, v.w};
#pragma unroll
            for (int j = 0; j < 4; ++j) {
                unsigned h = f2tf(vv[j]);
                AH[bo + j] = h;
                AL[bo + j] = f2tf(vv[j] - __uint_as_float(h));
            }
        }
#pragma unroll
        for (int i = 0; i < 4; ++i) {
            float4 v = rW[i];
            int bo = (wk + i * 8) * WP + wn4;
            float vv[4] = {v.x, v.y, v.z, v.w};
#pragma unroll
            for (int j = 0; j < 4; ++j) {
                unsigned h = f2tf(vv[j]);
                WH[bo + j] = h;
                WL[bo + j] = f2tf(vv[j] - __uint_as_float(h));
            }
        }
        __syncthreads();

        if (tile + 1 < ntiles) {
            const int nt = tile + 1;
            const float* A = (nt >> 2) ? A2 : A1;
            const float* W = (nt >> 2) ? W2 : W1;
            const int nk0 = (nt & 3) * 32;
#pragma unroll
            for (int i = 0; i < 4; ++i) {
                int grow = row0 + ar + i * 32;
                rA[i] = make_float4(0.f, 0.f, 0.f, 0.f);
                if (grow < NN) rA[i] = *(const float4*)(A + (size_t)grow * HH + nk0 + ac4);
            }
#pragma unroll
            for (int i = 0; i < 4; ++i)
                rW[i] = *(const float4*)(W + (size_t)(nk0 + wk + i * 8) * HH + wn4);
        }

#pragma unroll
        for (int ks = 0; ks < 4; ++ks) {
            int kb = ks * 8;
            unsigned ah[2][4], al[2][4];
#pragma unroll
            for (int mi = 0; mi < 2; ++mi) {
                int rb = (warpM * 32 + mi * 16 + g) * AP + kb + t;
                ah[mi][0] = AH[rb];
                ah[mi][1] = AH[rb + 8 * AP];
                ah[mi][2] = AH[rb + 4];
                ah[mi][3] = AH[rb + 8 * AP + 4];
                al[mi][0] = AL[rb];
                al[mi][1] = AL[rb + 8 * AP];
                al[mi][2] = AL[rb + 4];
                al[mi][3] = AL[rb + 8 * AP + 4];
            }
#pragma unroll
            for (int ni = 0; ni < 8; ++ni) {
                int col = warpN * 64 + ni * 8 + g;
                int wb = (kb + t) * WP + col;
                unsigned bh0 = WH[wb], bh1 = WH[wb + 4 * WP];
                unsigned bl0 = WL[wb], bl1 = WL[wb + 4 * WP];
#pragma unroll
                for (int mi = 0; mi < 2; ++mi) {
                    mma_tf32(acc[mi][ni], ah[mi], bh0, bh1);
                    mma_tf32(acc[mi][ni], ah[mi], bl0, bl1);
                    mma_tf32(acc[mi][ni], al[mi], bh0, bh1);
                }
            }
        }
    }

#pragma unroll
    for (int mi = 0; mi < 2; ++mi) {
        int rbase = row0 + warpM * 32 + mi * 16 + g;
#pragma unroll
        for (int ni = 0; ni < 8; ++ni) {
            int col = warpN * 64 + ni * 8 + 2 * t;
            float c0 = acc[mi][ni][0], c1 = acc[mi][ni][1];
            float c2 = acc[mi][ni][2], c3 = acc[mi][ni][3];
            if (dinv) {
                if (rbase < NN) {
                    float w = dinv[rbase]; w *= w;
                    *(float2*)(out1 + (size_t)rbase * HH + col) = make_float2(c0, c1);
                    *(float2*)(out2 + (size_t)rbase * HH + col) = make_float2(c0 * w, c1 * w);
                }
                if (rbase + 8 < NN) {
                    float w = dinv[rbase + 8]; w *= w;
                    *(float2*)(out1 + (size_t)(rbase + 8) * HH + col) = make_float2(c2, c3);
                    *(float2*)(out2 + (size_t)(rbase + 8) * HH + col) = make_float2(c2 * w, c3 * w);
                }
            } else {
                float b0 = bias_out[col], b1 = bias_out[col + 1];
                c0 += b0; c1 += b1; c2 += b0; c3 += b1;
                if (relu_out) {
                    c0 = fmaxf(c0, 0.f); c1 = fmaxf(c1, 0.f);
                    c2 = fmaxf(c2, 0.f); c3 = fmaxf(c3, 0.f);
                }
                if (rbase < NN)
                    *(float2*)(out1 + (size_t)rbase * HH + col) = make_float2(c0, c1);
                if (rbase + 8 < NN)
                    *(float2*)(out1 + (size_t)(rbase + 8) * HH + col) = make_float2(c2, c3);
            }
        }
    }
}

// ---------------- pooling: one warp per node ----------------
__global__ void k_pool(const float* __restrict__ h, const int* __restrict__ batch,
                       float* __restrict__ emb, float* __restrict__ cnt) {
    int i = (blockIdx.x * blockDim.x + threadIdx.x) >> 5;
    int lane = threadIdx.x & 31;
    if (i >= NN) return;
    int g = batch[i];
    float4 v = ((const float4*)(h + (size_t)i * HH))[lane];
    atomicAdd(((float4*)(emb + (size_t)g * HH)) + lane, v);
    if (lane == 0) atomicAdd(&cnt[g], 1.0f);
}

// ---------------- final head: mean (+b5) + linear ----------------
__global__ void k_final(const float* __restrict__ lin_w, const float* __restrict__ lin_b,
                        const float* __restrict__ b5,
                        const float* __restrict__ emb, const float* __restrict__ cnt,
                        float* __restrict__ out) {
    __shared__ float se[GG * HH];
    int tid = threadIdx.x;
    for (int i = tid; i < GG * HH; i += blockDim.x) {
        int g = i >> 7;
        int c = i & 127;
        float v = emb[i] / fmaxf(cnt[g], 1.0f) + b5[c];
        se[i] = v;
        out[GG * CC + i] = v;
    }
    __syncthreads();
    for (int i = tid; i < GG * CC; i += blockDim.x) {
        int g = i / CC, c = i % CC;
        float s = lin_b[c];
        const float* e = &se[g * HH];
#pragma unroll 4
        for (int k = 0; k < HH; ++k) s = fmaf(e[k], lin_w[k * CC + c], s);
        out[i] = s;
    }
}

// ---------------- launch ----------------
extern "C" void kernel_launch(void* const* d_in, const int* in_sizes, int n_in,
                              void* d_out, int out_size) {
    const float* x      = (const float*)d_in[0];
    const int*   ei     = (const int*)d_in[1];
    const int*   batch  = (const int*)d_in[2];
    const float* w1r    = (const float*)d_in[3];
    const float* w1rel  = (const float*)d_in[4];
    const float* b1     = (const float*)d_in[5];
    const float* w2r    = (const float*)d_in[6];
    const float* w2rel  = (const float*)d_in[7];
    const float* b2     = (const float*)d_in[8];
    const float* w3     = (const float*)d_in[9];
    const float* b3     = (const float*)d_in[10];
    const float* w4     = (const float*)d_in[11];
    const float* b4     = (const float*)d_in[12];
    const float* w5     = (const float*)d_in[13];
    const float* b5     = (const float*)d_in[14];
    const float* lin_w  = (const float*)d_in[15];
    const float* lin_b  = (const float*)d_in[16];
    float* out = (float*)d_out;

    const int* src = ei;
    const int* dst = ei + EE;

    float *B1, *B2, *B3, *DINV, *EMB, *CNT, *WNORM;
    int *DEG, *ROWS, *CUR, *CSRC, *BSUM, *BSCAN;
    cudaGetSymbolAddress((void**)&B1, g_b1);
    cudaGetSymbolAddress((void**)&B2, g_b2);
    cudaGetSymbolAddress((void**)&B3, g_b3);
    cudaGetSymbolAddress((void**)&DINV, g_dinv);
    cudaGetSymbolAddress((void**)&EMB, g_emb);
    cudaGetSymbolAddress((void**)&CNT, g_cnt);
    cudaGetSymbolAddress((void**)&DEG, g_deg);
    cudaGetSymbolAddress((void**)&ROWS, g_rowstart);
    cudaGetSymbolAddress((void**)&CUR, g_cursor);
    cudaGetSymbolAddress((void**)&CSRC, g_csrsrc);
    cudaGetSymbolAddress((void**)&WNORM, g_wnorm);
    cudaGetSymbolAddress((void**)&BSUM, g_bsum);
    cudaGetSymbolAddress((void**)&BSCAN, g_bscan);

    const int SMEM = (2 * ASZ + 2 * WSZ) * 4;   // 71680 B
    cudaFuncSetAttribute(k_gemm_tc, cudaFuncAttributeMaxDynamicSharedMemorySize, SMEM);

    const int NB  = (NN + 255) / 256;          // 157
    const int EB  = (EE + 255) / 256;
    const int GWB = (NN * 32 + 255) / 256;
    const int GMB = (NN + 127) / 128;          // 313

    // ---- CSR build (by destination), parallel scan ----
    k_zero_int<<<NB, 256>>>(DEG, NN);
    k_hist<<<EB, 256>>>(dst, DEG);
    k_bsum<<<NB2, 256>>>(DEG, BSUM);
    k_bscan<<<1, 256>>>(BSUM, BSCAN);
    k_writeoff<<<NB2, 256>>>(DEG, BSCAN, ROWS, CUR, DINV);
    k_fill<<<EB, 256>>>(src, dst, DINV, CUR, CSRC, WNORM);

    // ---- L1: GraphConv ----
    k_gather<<<GWB, 256>>>(x, B1, ROWS, CSRC, nullptr);
    k_gemm_tc<<<GMB, 256, SMEM>>>(x, w1r, B1, w1rel, nullptr, b1, nullptr, B2, nullptr, 1);

    // ---- L2: GraphConv ----
    k_gather<<<GWB, 256>>>(B2, B1, ROWS, CSRC, nullptr);
    k_gemm_tc<<<GMB, 256, SMEM>>>(B2, w2r, B1, w2rel, nullptr, b2, nullptr, B3, nullptr, 1);

    // ---- L3: GCNConv ----  raw h -> B2, self-term h*dinv^2 -> B1; gather adds into B1
    k_gemm_tc<<<GMB, 256, SMEM>>>(B3, w3, nullptr, nullptr, nullptr, nullptr, DINV, B2, B1, 0);
    k_gather<<<GWB, 256>>>(B2, B1, ROWS, CSRC, WNORM);

    // ---- L4: GCNConv (input +b3, relu on load) ----
    k_gemm_tc<<<GMB, 256, SMEM>>>(B1, w4, nullptr, nullptr, b3, nullptr, DINV, B2, B3, 0);
    k_gather<<<GWB, 256>>>(B2, B3, ROWS, CSRC, WNORM);

    // ---- L5: GCNConv (input +b4, relu on load) ----
    k_gemm_tc<<<GMB, 256, SMEM>>>(B3, w5, nullptr, nullptr, b4, nullptr, DINV, B2, B1, 0);
    k_gather<<<GWB, 256>>>(B2, B1, ROWS, CSRC, WNORM);

    // ---- pooling + head (b5 folded into final mean) ----
    k_zero4<<<(GG * HH / 4 + 255) / 256, 256>>>(EMB, GG * HH / 4);
    k_zero4<<<1, 32>>>(CNT, GG / 4);
    k_pool<<<GWB, 256>>>(B1, batch, EMB, CNT);
    k_final<<<1, 512>>>(lin_w, lin_b, b5, EMB, CNT, out);
}